// round 15
// baseline (speedup 1.0000x reference)
#include <cuda_runtime.h>
#include <math.h>

#define NN   8192     // nodes
#define FIN  64       // input features
#define HH   128      // hidden
#define AA   8192     // action size
#define CAP  128      // max unique out-degree bucket capacity
#define GROWS 64      // rows per fused-GEMM block

// ---------------- device scratch (static, zero-initialized) ----------------
static __device__ unsigned g_bitmap[NN * (NN / 32)];   // 8 MB dedup bitmap
static __device__ int      g_cnt[NN];                  // unique out-degree
static __device__ int      g_cols[NN * CAP];           // bucketed CSR cols (4 MB)
static __device__ float    g_ax[NN * FIN];             // A_n @ x
static __device__ float    g_Q [NN * HH];              // h1 @ g2W
static __device__ float    g_h2[NN * HH];              // layer-2 output
static __device__ float    g_rowsum[NN];
static __device__ float    g_graph[HH];
static __device__ float    g_af[64];                   // actor hidden
static __device__ float    g_logits[AA];
static __device__ float    g_red[2];                   // pool max, pool sumexp
static __device__ int      g_ctr0, g_ctr1, g_ctr2;     // last-block counters

// ---------------- kernels ----------------

// Dedup edges into bucketed CSR. Bitmap zero on entry (zero-init first launch,
// cleared concurrently later in every launch). int64 detection per-block.
__global__ void k_dedup(const int* __restrict__ e, int E) {
    __shared__ int s64;
    if (threadIdx.x == 0) {
        int all0 = 1;
        #pragma unroll
        for (int k = 0; k < 32; k++)
            if (e[2 * k + 1] != 0) all0 = 0;
        s64 = all0;
    }
    __syncthreads();
    int idx = blockIdx.x * blockDim.x + threadIdx.x;
    if (idx >= E) return;
    int r, c;
    if (s64) { r = e[2 * idx]; c = e[2 * (E + idx)]; }
    else     { r = e[idx];     c = e[E + idx]; }
    unsigned lin = (unsigned)r * NN + (unsigned)c;
    unsigned w = lin >> 5, b = lin & 31u;
    unsigned old = atomicOr(&g_bitmap[w], 1u << b);
    if (!((old >> b) & 1u)) {
        int pos = atomicAdd(&g_cnt[r], 1);
        if (pos < CAP) g_cols[r * CAP + pos] = c;
    }
}

// Clear the 8MB bitmap for the NEXT launch (overlapped with k_l12).
__global__ void k_clearbm() {
    const int total4 = (NN * (NN / 32)) / 4;
    uint4* bm = reinterpret_cast<uint4*>(g_bitmap);
    int i = blockIdx.x * blockDim.x + threadIdx.x;
    int stride = gridDim.x * blockDim.x;
    uint4 z = make_uint4(0u, 0u, 0u, 0u);
    for (int w = i; w < total4; w += stride) bm[w] = z;
}

// SpMM on input: ax = A_n @ x. Warp per row, float2 per lane (64 feats).
__global__ void __launch_bounds__(128) k_spmmx(const float* __restrict__ x) {
    __shared__ int   s_cols[4][CAP];
    __shared__ float s_dinv[4][CAP];
    int t = threadIdx.x, wid = t >> 5, lane = t & 31;
    int r = blockIdx.x * 4 + wid;
    int cnt = min(g_cnt[r], CAP);
    for (int k = lane; k < cnt; k += 32) {
        int c = g_cols[r * CAP + k];
        s_cols[wid][k] = c;
        s_dinv[wid][k] = rsqrtf((float)(min(g_cnt[c], CAP) + 1));
    }
    __syncwarp();
    float dr = rsqrtf((float)(cnt + 1));
    const float2* xv = reinterpret_cast<const float2*>(x);
    float2 self = xv[r * 32 + lane];
    float a0 = dr * self.x, a1 = dr * self.y;
    float b0 = 0.f, b1 = 0.f;
    int k = 0;
    #pragma unroll 2
    for (; k + 1 < cnt; k += 2) {
        int   c0 = s_cols[wid][k],   c1 = s_cols[wid][k + 1];
        float d0 = s_dinv[wid][k],   d1 = s_dinv[wid][k + 1];
        float2 v0 = xv[c0 * 32 + lane];
        float2 v1 = xv[c1 * 32 + lane];
        a0 += d0 * v0.x; a1 += d0 * v0.y;
        b0 += d1 * v1.x; b1 += d1 * v1.y;
    }
    if (k < cnt) {
        int c = s_cols[wid][k]; float d = s_dinv[wid][k];
        float2 v = xv[c * 32 + lane];
        a0 += d * v.x; a1 += d * v.y;
    }
    reinterpret_cast<float2*>(g_ax)[r * 32 + lane] =
        make_float2(dr * (a0 + b0), dr * (a1 + b1));
}

// Fused res + layer1 + layer2-GEMM. 64 rows/block, 512 threads, 96 KB smem.
// P0: accR = x@resW + resb (registers)
// P1: h1 = relu(ax@g1W + g1b) + accR  -> smem HT[row*128+col]
// P2: Q = h1 @ g2W                     -> g_Q
// smem floats: sW[0,16384) (P0/P1 use first 8192 for W, [8192,12288) for acts;
//              P2 loads g2W over the whole region), HT[16384,24576). 96KB.
__global__ void __launch_bounds__(512) k_l12(const float* __restrict__ x,
                      const float* __restrict__ resW, const float* __restrict__ resb,
                      const float* __restrict__ g1W,  const float* __restrict__ g1b,
                      const float* __restrict__ g2W) {
    extern __shared__ float sm[];
    float* sW = sm;            // weights
    float* sA = sm + 8192;     // transposed acts [k*64 + r]
    float* sH = sm + 16384;    // h1 tile [row*128 + col]
    int r0 = blockIdx.x * GROWS;
    int t = threadIdx.x;
    int tx = t & 31, w4 = (t >> 5) * 4;

    // ---- P0: residual GEMM ----
    {
        float4* dw = reinterpret_cast<float4*>(sW);
        const float4* swr = reinterpret_cast<const float4*>(resW);
        #pragma unroll
        for (int u = 0; u < 4; u++) dw[t + u * 512] = swr[t + u * 512];
        const float4* sx = reinterpret_cast<const float4*>(x) + r0 * (FIN / 4);
        #pragma unroll
        for (int uu = 0; uu < 2; uu++) {
            int u = t + uu * 512;
            int r = u & 63, k4 = u >> 6;
            float4 vx = sx[r * 16 + k4];
            int kb = k4 * 4;
            sA[(kb + 0) * 64 + r] = vx.x; sA[(kb + 1) * 64 + r] = vx.y;
            sA[(kb + 2) * 64 + r] = vx.z; sA[(kb + 3) * 64 + r] = vx.w;
        }
    }
    __syncthreads();
    float accR[4][4];
    #pragma unroll
    for (int i = 0; i < 4; i++)
        #pragma unroll
        for (int c = 0; c < 4; c++) accR[i][c] = 0.f;
    #pragma unroll 4
    for (int k = 0; k < FIN; k++) {
        float4 w = *reinterpret_cast<const float4*>(&sW[k * HH + tx * 4]);
        float4 a = *reinterpret_cast<const float4*>(&sA[k * 64 + w4]);
        float ar[4] = {a.x, a.y, a.z, a.w};
        #pragma unroll
        for (int i = 0; i < 4; i++) {
            accR[i][0] += ar[i] * w.x; accR[i][1] += ar[i] * w.y;
            accR[i][2] += ar[i] * w.z; accR[i][3] += ar[i] * w.w;
        }
    }
    {
        float4 br = reinterpret_cast<const float4*>(resb)[tx];
        #pragma unroll
        for (int i = 0; i < 4; i++) {
            accR[i][0] += br.x; accR[i][1] += br.y;
            accR[i][2] += br.z; accR[i][3] += br.w;
        }
    }
    __syncthreads();

    // ---- P1: layer-1 GEMM ----
    {
        float4* dw = reinterpret_cast<float4*>(sW);
        const float4* sg = reinterpret_cast<const float4*>(g1W);
        #pragma unroll
        for (int u = 0; u < 4; u++) dw[t + u * 512] = sg[t + u * 512];
        const float4* sa = reinterpret_cast<const float4*>(g_ax) + r0 * (FIN / 4);
        #pragma unroll
        for (int uu = 0; uu < 2; uu++) {
            int u = t + uu * 512;
            int r = u & 63, k4 = u >> 6;
            float4 va = sa[r * 16 + k4];
            int kb = k4 * 4;
            sA[(kb + 0) * 64 + r] = va.x; sA[(kb + 1) * 64 + r] = va.y;
            sA[(kb + 2) * 64 + r] = va.z; sA[(kb + 3) * 64 + r] = va.w;
        }
    }
    __syncthreads();
    float accP[4][4];
    #pragma unroll
    for (int i = 0; i < 4; i++)
        #pragma unroll
        for (int c = 0; c < 4; c++) accP[i][c] = 0.f;
    #pragma unroll 4
    for (int k = 0; k < FIN; k++) {
        float4 w = *reinterpret_cast<const float4*>(&sW[k * HH + tx * 4]);
        float4 a = *reinterpret_cast<const float4*>(&sA[k * 64 + w4]);
        float ar[4] = {a.x, a.y, a.z, a.w};
        #pragma unroll
        for (int i = 0; i < 4; i++) {
            accP[i][0] += ar[i] * w.x; accP[i][1] += ar[i] * w.y;
            accP[i][2] += ar[i] * w.z; accP[i][3] += ar[i] * w.w;
        }
    }
    {
        float4 bg = reinterpret_cast<const float4*>(g1b)[tx];
        #pragma unroll
        for (int i = 0; i < 4; i++) {
            float4 o;
            o.x = fmaxf(accP[i][0] + bg.x, 0.f) + accR[i][0];
            o.y = fmaxf(accP[i][1] + bg.y, 0.f) + accR[i][1];
            o.z = fmaxf(accP[i][2] + bg.z, 0.f) + accR[i][2];
            o.w = fmaxf(accP[i][3] + bg.w, 0.f) + accR[i][3];
            *reinterpret_cast<float4*>(&sH[(w4 + i) * HH + tx * 4]) = o;
        }
    }
    __syncthreads();

    // ---- P2: layer-2 GEMM from smem h1 ----
    {
        float4* dw = reinterpret_cast<float4*>(sW);
        const float4* sg = reinterpret_cast<const float4*>(g2W);
        #pragma unroll
        for (int u = 0; u < 8; u++) dw[t + u * 512] = sg[t + u * 512];
    }
    __syncthreads();
    float acc[4][4];
    #pragma unroll
    for (int i = 0; i < 4; i++)
        #pragma unroll
        for (int c = 0; c < 4; c++) acc[i][c] = 0.f;
    #pragma unroll 2
    for (int k4 = 0; k4 < HH / 4; k4++) {
        int k = k4 * 4;
        float4 w0 = *reinterpret_cast<const float4*>(&sW[(k + 0) * HH + tx * 4]);
        float4 w1 = *reinterpret_cast<const float4*>(&sW[(k + 1) * HH + tx * 4]);
        float4 w2 = *reinterpret_cast<const float4*>(&sW[(k + 2) * HH + tx * 4]);
        float4 w3 = *reinterpret_cast<const float4*>(&sW[(k + 3) * HH + tx * 4]);
        #pragma unroll
        for (int i = 0; i < 4; i++) {
            float4 h = *reinterpret_cast<const float4*>(&sH[(w4 + i) * HH + k]);  // broadcast
            acc[i][0] += h.x * w0.x + h.y * w1.x + h.z * w2.x + h.w * w3.x;
            acc[i][1] += h.x * w0.y + h.y * w1.y + h.z * w2.y + h.w * w3.y;
            acc[i][2] += h.x * w0.z + h.y * w1.z + h.z * w2.z + h.w * w3.z;
            acc[i][3] += h.x * w0.w + h.y * w1.w + h.z * w2.w + h.w * w3.w;
        }
    }
    #pragma unroll
    for (int i = 0; i < 4; i++) {
        int row = r0 + w4 + i;
        reinterpret_cast<float4*>(g_Q)[row * 32 + tx] =
            make_float4(acc[i][0], acc[i][1], acc[i][2], acc[i][3]);
    }
}

// SpMM2: h2 = relu(A_n Q + g2b), rowsum. Warp per row, float4 per lane.
// Last block: pooling softmax stats + zero g_graph.
__global__ void __launch_bounds__(128) k_spmm2(const float* __restrict__ g2b) {
    __shared__ int   s_cols[4][CAP];
    __shared__ float s_dinv[4][CAP];
    __shared__ float s_m[4];
    __shared__ float s_bm;
    __shared__ int   s_last;
    int t = threadIdx.x, wid = t >> 5, lane = t & 31;
    int r = blockIdx.x * 4 + wid;
    int cnt = min(g_cnt[r], CAP);
    for (int k = lane; k < cnt; k += 32) {
        int c = g_cols[r * CAP + k];
        s_cols[wid][k] = c;
        s_dinv[wid][k] = rsqrtf((float)(min(g_cnt[c], CAP) + 1));
    }
    __syncwarp();
    float dr = rsqrtf((float)(cnt + 1));
    const float4* Qv = reinterpret_cast<const float4*>(g_Q);
    float4 self = Qv[r * 32 + lane];
    float a0 = dr * self.x, a1 = dr * self.y, a2 = dr * self.z, a3 = dr * self.w;
    float b0 = 0.f, b1 = 0.f, b2 = 0.f, b3 = 0.f;
    int k = 0;
    #pragma unroll 2
    for (; k + 1 < cnt; k += 2) {
        int   c0 = s_cols[wid][k],   c1 = s_cols[wid][k + 1];
        float d0 = s_dinv[wid][k],   d1 = s_dinv[wid][k + 1];
        float4 v0 = Qv[c0 * 32 + lane];
        float4 v1 = Qv[c1 * 32 + lane];
        a0 += d0 * v0.x; a1 += d0 * v0.y; a2 += d0 * v0.z; a3 += d0 * v0.w;
        b0 += d1 * v1.x; b1 += d1 * v1.y; b2 += d1 * v1.z; b3 += d1 * v1.w;
    }
    if (k < cnt) {
        int c = s_cols[wid][k]; float d = s_dinv[wid][k];
        float4 v = Qv[c * 32 + lane];
        a0 += d * v.x; a1 += d * v.y; a2 += d * v.z; a3 += d * v.w;
    }
    float4 bias = reinterpret_cast<const float4*>(g2b)[lane];
    float h0 = fmaxf(dr * (a0 + b0) + bias.x, 0.f);
    float h1v = fmaxf(dr * (a1 + b1) + bias.y, 0.f);
    float h2v = fmaxf(dr * (a2 + b2) + bias.z, 0.f);
    float h3 = fmaxf(dr * (a3 + b3) + bias.w, 0.f);
    reinterpret_cast<float4*>(g_h2)[r * 32 + lane] = make_float4(h0, h1v, h2v, h3);
    float v = h0 + h1v + h2v + h3;
    #pragma unroll
    for (int o = 16; o > 0; o >>= 1) v += __shfl_down_sync(0xffffffffu, v, o);
    if (lane == 0) g_rowsum[r] = v;

    __syncthreads();
    __threadfence();
    if (t == 0) {
        int done = atomicAdd(&g_ctr0, 1);
        s_last = (done == (int)gridDim.x - 1);
    }
    __syncthreads();
    if (!s_last) return;
    g_graph[t] = 0.f;
    float m = -1e30f;
    for (int j = t; j < NN; j += 128) m = fmaxf(m, g_rowsum[j]);
    #pragma unroll
    for (int o = 16; o > 0; o >>= 1) m = fmaxf(m, __shfl_down_sync(0xffffffffu, m, o));
    if ((t & 31) == 0) s_m[t >> 5] = m;
    __syncthreads();
    if (t == 0) s_bm = fmaxf(fmaxf(s_m[0], s_m[1]), fmaxf(s_m[2], s_m[3]));
    __syncthreads();
    float bm = s_bm;
    float s = 0.f;
    for (int j = t; j < NN; j += 128) s += expf(g_rowsum[j] - bm);
    #pragma unroll
    for (int o = 16; o > 0; o >>= 1) s += __shfl_down_sync(0xffffffffu, s, o);
    __syncthreads();
    if ((t & 31) == 0) s_m[t >> 5] = s;
    __syncthreads();
    if (t == 0) {
        g_red[0] = bm;
        g_red[1] = s_m[0] + s_m[1] + s_m[2] + s_m[3];
        g_ctr0 = 0;
    }
}

// Pool + (last block) heads.
__global__ void __launch_bounds__(128) k_pool(const float* __restrict__ a1W, const float* __restrict__ a1b,
                        const float* __restrict__ lng, const float* __restrict__ lnb,
                        const float* __restrict__ c1W, const float* __restrict__ c1b,
                        const float* __restrict__ c2W, const float* __restrict__ c2b,
                        float* __restrict__ out, int out_size) {
    __shared__ float s_w[64];
    __shared__ float s_g[HH], s_z[HH], s_c[64];
    __shared__ float sm[4];
    __shared__ int   s_last;
    int t = threadIdx.x;
    int r0 = blockIdx.x * 64;
    if (t < 64) s_w[t] = expf(g_rowsum[r0 + t] - g_red[0]) * (1.0f / g_red[1]);
    __syncthreads();
    float acc = 0.f;
    #pragma unroll 4
    for (int j = 0; j < 64; j++) acc += s_w[j] * g_h2[(r0 + j) * HH + t];
    atomicAdd(&g_graph[t], acc);

    __threadfence();
    if (t == 0) {
        int done = atomicAdd(&g_ctr1, 1);
        s_last = (done == (int)gridDim.x - 1);
    }
    __syncthreads();
    if (!s_last) return;

    s_g[t] = g_graph[t];
    __syncthreads();
    if (t < 64) {
        float a = a1b[t];
        #pragma unroll 8
        for (int k = 0; k < HH; k++) a += s_g[k] * a1W[k * 64 + t];
        g_af[t] = fmaxf(a, 0.f);
    }
    float v = s_g[t];
    #pragma unroll
    for (int o = 16; o > 0; o >>= 1) v += __shfl_down_sync(0xffffffffu, v, o);
    if ((t & 31) == 0) sm[t >> 5] = v;
    __syncthreads();
    float mu = (sm[0] + sm[1] + sm[2] + sm[3]) * (1.0f / HH);
    __syncthreads();
    float d = s_g[t] - mu;
    float v2 = d * d;
    #pragma unroll
    for (int o = 16; o > 0; o >>= 1) v2 += __shfl_down_sync(0xffffffffu, v2, o);
    if ((t & 31) == 0) sm[t >> 5] = v2;
    __syncthreads();
    float var = (sm[0] + sm[1] + sm[2] + sm[3]) * (1.0f / HH);
    s_z[t] = d / sqrtf(var + 1e-5f) * lng[t] + lnb[t];
    __syncthreads();
    if (t < 64) {
        float c = c1b[t];
        #pragma unroll 8
        for (int k = 0; k < HH; k++) c += s_z[k] * c1W[k * 64 + t];
        s_c[t] = fmaxf(c, 0.f);
    }
    __syncthreads();
    if (t == 0) {
        float val = c2b[0];
        #pragma unroll 8
        for (int j = 0; j < 64; j++) val += s_c[j] * c2W[j];
        if (out_size > NN) out[NN] = val;
        g_ctr1 = 0;
    }
}

// Actor logits; clears g_cnt for next launch; last block: softmax + output.
__global__ void __launch_bounds__(256) k_act(const float* __restrict__ a2W, const float* __restrict__ a2b,
                       float* __restrict__ out) {
    __shared__ float s_af[64];
    __shared__ float sm[8];
    __shared__ float s_bm;
    __shared__ int   s_last;
    int t = threadIdx.x;
    if (t < 64) s_af[t] = g_af[t];
    __syncthreads();
    int o = blockIdx.x * 256 + t;
    float acc = a2b[o];
    #pragma unroll
    for (int j = 0; j < 64; j++) acc += s_af[j] * a2W[j * AA + o];
    g_logits[o] = acc;
    g_cnt[o] = 0;               // clear degree array for next launch (8192 == AA)

    __threadfence();
    if (t == 0) {
        int done = atomicAdd(&g_ctr2, 1);
        s_last = (done == (int)gridDim.x - 1);
    }
    __syncthreads();
    if (!s_last) return;

    float m = -1e30f;
    for (int j = t; j < AA; j += 256) m = fmaxf(m, g_logits[j]);
    #pragma unroll
    for (int ofs = 16; ofs > 0; ofs >>= 1) m = fmaxf(m, __shfl_down_sync(0xffffffffu, m, ofs));
    if ((t & 31) == 0) sm[t >> 5] = m;
    __syncthreads();
    if (t == 0) {
        float x = sm[0];
        #pragma unroll
        for (int j = 1; j < 8; j++) x = fmaxf(x, sm[j]);
        s_bm = x;
    }
    __syncthreads();
    float bm = s_bm;
    float s = 0.f;
    for (int j = t; j < AA; j += 256) s += expf(g_logits[j] - bm);
    #pragma unroll
    for (int ofs = 16; ofs > 0; ofs >>= 1) s += __shfl_down_sync(0xffffffffu, s, ofs);
    __syncthreads();
    if ((t & 31) == 0) sm[t >> 5] = s;
    __syncthreads();
    if (t == 0) {
        float x = 0.f;
        #pragma unroll
        for (int j = 0; j < 8; j++) x += sm[j];
        s_bm = 1.0f / x;
        g_ctr2 = 0;
    }
    __syncthreads();
    float inv = s_bm;
    for (int j = t; j < AA; j += 256) out[j] = expf(g_logits[j] - bm) * inv;
}

// ---------------- launch ----------------
extern "C" void kernel_launch(void* const* d_in, const int* in_sizes, int n_in,
                              void* d_out, int out_size) {
    const float* x    = (const float*)d_in[0];
    const int*   ei   = (const int*)  d_in[1];
    int E = in_sizes[1] / 2;
    const float* g1W  = (const float*)d_in[2];
    const float* g1b  = (const float*)d_in[3];
    const float* g2W  = (const float*)d_in[4];
    const float* g2b  = (const float*)d_in[5];
    const float* resW = (const float*)d_in[6];
    const float* resb = (const float*)d_in[7];
    const float* a1W  = (const float*)d_in[8];
    const float* a1b  = (const float*)d_in[9];
    const float* a2W  = (const float*)d_in[10];
    const float* a2b  = (const float*)d_in[11];
    const float* lng  = (const float*)d_in[12];
    const float* lnb  = (const float*)d_in[13];
    const float* c1W  = (const float*)d_in[14];
    const float* c1b  = (const float*)d_in[15];
    const float* c2W  = (const float*)d_in[16];
    const float* c2b  = (const float*)d_in[17];
    float* out = (float*)d_out;

    const int SMEM96 = 96 * 1024;
    static cudaStream_t s2 = nullptr;
    static cudaEvent_t evX = nullptr, evC = nullptr;
    if (!s2) {
        cudaFuncSetAttribute(k_l12, cudaFuncAttributeMaxDynamicSharedMemorySize, SMEM96);
        cudaStreamCreateWithFlags(&s2, cudaStreamNonBlocking);
        cudaEventCreateWithFlags(&evX, cudaEventDisableTiming);
        cudaEventCreateWithFlags(&evC, cudaEventDisableTiming);
    }

    k_dedup<<<(E + 255) / 256, 256>>>(ei, E);
    k_spmmx<<<NN / 4, 128>>>(x);
    cudaEventRecord(evX, 0);

    // bitmap clear for NEXT launch, overlapped with the fused GEMM (idle SMs)
    cudaStreamWaitEvent(s2, evX, 0);
    k_clearbm<<<1024, 512, 0, s2>>>();
    cudaEventRecord(evC, s2);

    k_l12  <<<NN / GROWS, 512, SMEM96>>>(x, resW, resb, g1W, g1b, g2W);
    k_spmm2<<<NN / 4, 128>>>(g2b);
    k_pool <<<128, 128>>>(a1W, a1b, lng, lnb, c1W, c1b, c2W, c2b, out, out_size);
    cudaStreamWaitEvent(0, evC, 0);
    k_act  <<<32, 256>>>(a2W, a2b, out);
}

// round 16
// speedup vs baseline: 1.1721x; 1.1721x over previous
#include <cuda_runtime.h>
#include <math.h>

#define NN   8192     // nodes
#define FIN  64       // input features
#define HH   128      // hidden
#define AA   8192     // action size
#define CAP  128      // max unique out-degree bucket capacity
#define GROWS 64      // rows per GEMM block

// ---------------- device scratch (static, zero-initialized) ----------------
static __device__ int      g_tag[NN * NN];             // 256 MB generation tags
static __device__ int      g_gen = 1;                  // generation counter
static __device__ int      g_cnt[NN];                  // unique out-degree
static __device__ int      g_cols[NN * CAP];           // bucketed CSR cols (4 MB)
static __device__ float    g_ax[NN * FIN];             // A_n @ x
static __device__ float    g_h1[NN * HH];              // layer-1 output
static __device__ float    g_Q [NN * HH];              // h1 @ g2W
static __device__ float    g_h2[NN * HH];              // layer-2 output
static __device__ float    g_rowsum[NN];
static __device__ float    g_graph[HH];
static __device__ float    g_af[64];                   // actor hidden
static __device__ float    g_logits[AA];
static __device__ float    g_red[2];                   // pool max, pool sumexp
static __device__ int      g_ctr0, g_ctr1, g_ctr2;     // last-block counters

// ---------------- kernels ----------------

// Dedup edges into bucketed CSR via generation tags (no clearing needed:
// g_gen is bumped at the end of every launch by k_act's last block).
// int64-vs-int32 edge layout detected per-block.
__global__ void k_dedup(const int* __restrict__ e, int E) {
    __shared__ int s64, sgen;
    if (threadIdx.x == 0) {
        int all0 = 1;
        #pragma unroll
        for (int k = 0; k < 32; k++)
            if (e[2 * k + 1] != 0) all0 = 0;
        s64 = all0;
        sgen = g_gen;
    }
    __syncthreads();
    int idx = blockIdx.x * blockDim.x + threadIdx.x;
    if (idx >= E) return;
    int r, c;
    if (s64) { r = e[2 * idx]; c = e[2 * (E + idx)]; }
    else     { r = e[idx];     c = e[E + idx]; }
    unsigned lin = (unsigned)r * NN + (unsigned)c;
    int old = atomicExch(&g_tag[lin], sgen);
    if (old != sgen) {
        int pos = atomicAdd(&g_cnt[r], 1);
        if (pos < CAP) g_cols[r * CAP + pos] = c;
    }
}

// SpMM on input: ax = A_n @ x. Warp per row, float2 per lane (64 feats).
__global__ void __launch_bounds__(128) k_spmmx(const float* __restrict__ x) {
    __shared__ int   s_cols[4][CAP];
    __shared__ float s_dinv[4][CAP];
    int t = threadIdx.x, wid = t >> 5, lane = t & 31;
    int r = blockIdx.x * 4 + wid;
    int cnt = min(g_cnt[r], CAP);
    for (int k = lane; k < cnt; k += 32) {
        int c = g_cols[r * CAP + k];
        s_cols[wid][k] = c;
        s_dinv[wid][k] = rsqrtf((float)(min(g_cnt[c], CAP) + 1));
    }
    __syncwarp();
    float dr = rsqrtf((float)(cnt + 1));
    const float2* xv = reinterpret_cast<const float2*>(x);
    float2 self = xv[r * 32 + lane];
    float a0 = dr * self.x, a1 = dr * self.y;
    float b0 = 0.f, b1 = 0.f;
    int k = 0;
    #pragma unroll 2
    for (; k + 1 < cnt; k += 2) {
        int   c0 = s_cols[wid][k],   c1 = s_cols[wid][k + 1];
        float d0 = s_dinv[wid][k],   d1 = s_dinv[wid][k + 1];
        float2 v0 = xv[c0 * 32 + lane];
        float2 v1 = xv[c1 * 32 + lane];
        a0 += d0 * v0.x; a1 += d0 * v0.y;
        b0 += d1 * v1.x; b1 += d1 * v1.y;
    }
    if (k < cnt) {
        int c = s_cols[wid][k]; float d = s_dinv[wid][k];
        float2 v = xv[c * 32 + lane];
        a0 += d * v.x; a1 += d * v.y;
    }
    reinterpret_cast<float2*>(g_ax)[r * 32 + lane] =
        make_float2(dr * (a0 + b0), dr * (a1 + b1));
}

// Fused layer-1 GEMM, weights in smem, transposed acts (conflict-free fill):
// h1 = relu(ax@g1W + g1b) + (x@resW + resb). 64 rows/block, 512 threads.
// smem floats: W1[0,8192) WR[8192,16384) AXT[16384,20480) XT[20480,24576) = 96KB
__global__ void __launch_bounds__(512) k_l1(const float* __restrict__ x,
                      const float* __restrict__ g1W, const float* __restrict__ g1b,
                      const float* __restrict__ resW, const float* __restrict__ resb) {
    extern __shared__ float sm[];
    float* sW1 = sm;
    float* sWR = sm + 8192;
    float* sAX = sm + 16384;   // [k*64 + r]
    float* sX  = sm + 20480;   // [k*64 + r]
    int r0 = blockIdx.x * GROWS;
    int t = threadIdx.x;
    {
        float4* d1 = reinterpret_cast<float4*>(sW1);
        float4* d2 = reinterpret_cast<float4*>(sWR);
        const float4* s1 = reinterpret_cast<const float4*>(g1W);
        const float4* s2 = reinterpret_cast<const float4*>(resW);
        #pragma unroll
        for (int u = 0; u < 4; u++) { d1[t + u * 512] = s1[t + u * 512]; d2[t + u * 512] = s2[t + u * 512]; }
        const float4* sa = reinterpret_cast<const float4*>(g_ax) + r0 * (FIN / 4);
        const float4* sx = reinterpret_cast<const float4*>(x)    + r0 * (FIN / 4);
        #pragma unroll
        for (int uu = 0; uu < 2; uu++) {
            int u = t + uu * 512;
            int r = u & 63, k4 = u >> 6;
            float4 va = sa[r * 16 + k4];
            float4 vx = sx[r * 16 + k4];
            int kb = k4 * 4;
            sAX[(kb + 0) * 64 + r] = va.x; sAX[(kb + 1) * 64 + r] = va.y;
            sAX[(kb + 2) * 64 + r] = va.z; sAX[(kb + 3) * 64 + r] = va.w;
            sX [(kb + 0) * 64 + r] = vx.x; sX [(kb + 1) * 64 + r] = vx.y;
            sX [(kb + 2) * 64 + r] = vx.z; sX [(kb + 3) * 64 + r] = vx.w;
        }
    }
    __syncthreads();
    int tx = t & 31, w4 = (t >> 5) * 4;
    float accP[4][4], accR[4][4];
    #pragma unroll
    for (int i = 0; i < 4; i++)
        #pragma unroll
        for (int c = 0; c < 4; c++) { accP[i][c] = 0.f; accR[i][c] = 0.f; }
    #pragma unroll 4
    for (int k = 0; k < FIN; k++) {
        float4 w1 = *reinterpret_cast<const float4*>(&sW1[k * HH + tx * 4]);
        float4 wr = *reinterpret_cast<const float4*>(&sWR[k * HH + tx * 4]);
        float4 a  = *reinterpret_cast<const float4*>(&sAX[k * 64 + w4]);   // broadcast
        float4 xx = *reinterpret_cast<const float4*>(&sX [k * 64 + w4]);   // broadcast
        float ar[4] = {a.x, a.y, a.z, a.w};
        float xr[4] = {xx.x, xx.y, xx.z, xx.w};
        #pragma unroll
        for (int i = 0; i < 4; i++) {
            accP[i][0] += ar[i] * w1.x; accP[i][1] += ar[i] * w1.y;
            accP[i][2] += ar[i] * w1.z; accP[i][3] += ar[i] * w1.w;
            accR[i][0] += xr[i] * wr.x; accR[i][1] += xr[i] * wr.y;
            accR[i][2] += xr[i] * wr.z; accR[i][3] += xr[i] * wr.w;
        }
    }
    float4 bg = reinterpret_cast<const float4*>(g1b)[tx];
    float4 br = reinterpret_cast<const float4*>(resb)[tx];
    #pragma unroll
    for (int i = 0; i < 4; i++) {
        int row = r0 + w4 + i;
        float4 o;
        o.x = fmaxf(accP[i][0] + bg.x, 0.f) + accR[i][0] + br.x;
        o.y = fmaxf(accP[i][1] + bg.y, 0.f) + accR[i][1] + br.y;
        o.z = fmaxf(accP[i][2] + bg.z, 0.f) + accR[i][2] + br.z;
        o.w = fmaxf(accP[i][3] + bg.w, 0.f) + accR[i][3] + br.w;
        reinterpret_cast<float4*>(g_h1)[row * 32 + tx] = o;
    }
}

// GEMM2: Q = h1 @ g2W. Weights in smem, transposed acts. 64 rows, 512 threads.
// smem floats: W[0,16384) HT[16384,24576) = 96KB. HT: [k*64 + r].
__global__ void __launch_bounds__(512) k_gemm2(const float* __restrict__ g2W) {
    extern __shared__ float sm[];
    float* sW = sm;
    float* sH = sm + 16384;    // [k*64 + r]
    int r0 = blockIdx.x * GROWS;
    int t = threadIdx.x;
    {
        float4* dw = reinterpret_cast<float4*>(sW);
        const float4* swg = reinterpret_cast<const float4*>(g2W);
        #pragma unroll
        for (int u = 0; u < 8; u++) dw[t + u * 512] = swg[t + u * 512];
        const float4* sh = reinterpret_cast<const float4*>(g_h1) + r0 * (HH / 4);
        #pragma unroll
        for (int uu = 0; uu < 4; uu++) {
            int u = t + uu * 512;
            int r = u & 63, k4 = u >> 6;
            float4 vh = sh[r * 32 + k4];
            int kb = k4 * 4;
            sH[(kb + 0) * 64 + r] = vh.x; sH[(kb + 1) * 64 + r] = vh.y;
            sH[(kb + 2) * 64 + r] = vh.z; sH[(kb + 3) * 64 + r] = vh.w;
        }
    }
    __syncthreads();
    int tx = t & 31, w4 = (t >> 5) * 4;
    float acc[4][4];
    #pragma unroll
    for (int i = 0; i < 4; i++)
        #pragma unroll
        for (int c = 0; c < 4; c++) acc[i][c] = 0.f;
    #pragma unroll 4
    for (int k = 0; k < HH; k++) {
        float4 w = *reinterpret_cast<const float4*>(&sW[k * HH + tx * 4]);
        float4 h = *reinterpret_cast<const float4*>(&sH[k * 64 + w4]);     // broadcast
        float hr[4] = {h.x, h.y, h.z, h.w};
        #pragma unroll
        for (int i = 0; i < 4; i++) {
            acc[i][0] += hr[i] * w.x; acc[i][1] += hr[i] * w.y;
            acc[i][2] += hr[i] * w.z; acc[i][3] += hr[i] * w.w;
        }
    }
    #pragma unroll
    for (int i = 0; i < 4; i++) {
        int row = r0 + w4 + i;
        reinterpret_cast<float4*>(g_Q)[row * 32 + tx] =
            make_float4(acc[i][0], acc[i][1], acc[i][2], acc[i][3]);
    }
}

// SpMM2: h2 = relu(A_n Q + g2b), rowsum. Warp per row, float4 per lane.
// Last block: pooling softmax stats + zero g_graph for k_pool.
__global__ void __launch_bounds__(128) k_spmm2(const float* __restrict__ g2b) {
    __shared__ int   s_cols[4][CAP];
    __shared__ float s_dinv[4][CAP];
    __shared__ float s_m[4];
    __shared__ float s_bm;
    __shared__ int   s_last;
    int t = threadIdx.x, wid = t >> 5, lane = t & 31;
    int r = blockIdx.x * 4 + wid;
    int cnt = min(g_cnt[r], CAP);
    for (int k = lane; k < cnt; k += 32) {
        int c = g_cols[r * CAP + k];
        s_cols[wid][k] = c;
        s_dinv[wid][k] = rsqrtf((float)(min(g_cnt[c], CAP) + 1));
    }
    __syncwarp();
    float dr = rsqrtf((float)(cnt + 1));
    const float4* Qv = reinterpret_cast<const float4*>(g_Q);
    float4 self = Qv[r * 32 + lane];
    float a0 = dr * self.x, a1 = dr * self.y, a2 = dr * self.z, a3 = dr * self.w;
    float b0 = 0.f, b1 = 0.f, b2 = 0.f, b3 = 0.f;
    int k = 0;
    #pragma unroll 2
    for (; k + 1 < cnt; k += 2) {
        int   c0 = s_cols[wid][k],   c1 = s_cols[wid][k + 1];
        float d0 = s_dinv[wid][k],   d1 = s_dinv[wid][k + 1];
        float4 v0 = Qv[c0 * 32 + lane];
        float4 v1 = Qv[c1 * 32 + lane];
        a0 += d0 * v0.x; a1 += d0 * v0.y; a2 += d0 * v0.z; a3 += d0 * v0.w;
        b0 += d1 * v1.x; b1 += d1 * v1.y; b2 += d1 * v1.z; b3 += d1 * v1.w;
    }
    if (k < cnt) {
        int c = s_cols[wid][k]; float d = s_dinv[wid][k];
        float4 v = Qv[c * 32 + lane];
        a0 += d * v.x; a1 += d * v.y; a2 += d * v.z; a3 += d * v.w;
    }
    float4 bias = reinterpret_cast<const float4*>(g2b)[lane];
    float h0 = fmaxf(dr * (a0 + b0) + bias.x, 0.f);
    float h1v = fmaxf(dr * (a1 + b1) + bias.y, 0.f);
    float h2v = fmaxf(dr * (a2 + b2) + bias.z, 0.f);
    float h3 = fmaxf(dr * (a3 + b3) + bias.w, 0.f);
    reinterpret_cast<float4*>(g_h2)[r * 32 + lane] = make_float4(h0, h1v, h2v, h3);
    float v = h0 + h1v + h2v + h3;
    #pragma unroll
    for (int o = 16; o > 0; o >>= 1) v += __shfl_down_sync(0xffffffffu, v, o);
    if (lane == 0) g_rowsum[r] = v;

    __syncthreads();
    __threadfence();
    if (t == 0) {
        int done = atomicAdd(&g_ctr0, 1);
        s_last = (done == (int)gridDim.x - 1);
    }
    __syncthreads();
    if (!s_last) return;
    g_graph[t] = 0.f;   // zero pool accumulator for k_pool
    float m = -1e30f;
    for (int j = t; j < NN; j += 128) m = fmaxf(m, g_rowsum[j]);
    #pragma unroll
    for (int o = 16; o > 0; o >>= 1) m = fmaxf(m, __shfl_down_sync(0xffffffffu, m, o));
    if ((t & 31) == 0) s_m[t >> 5] = m;
    __syncthreads();
    if (t == 0) s_bm = fmaxf(fmaxf(s_m[0], s_m[1]), fmaxf(s_m[2], s_m[3]));
    __syncthreads();
    float bm = s_bm;
    float s = 0.f;
    for (int j = t; j < NN; j += 128) s += expf(g_rowsum[j] - bm);
    #pragma unroll
    for (int o = 16; o > 0; o >>= 1) s += __shfl_down_sync(0xffffffffu, s, o);
    __syncthreads();
    if ((t & 31) == 0) s_m[t >> 5] = s;
    __syncthreads();
    if (t == 0) {
        g_red[0] = bm;
        g_red[1] = s_m[0] + s_m[1] + s_m[2] + s_m[3];
        g_ctr0 = 0;
    }
}

// Pool + (last block) heads.
__global__ void __launch_bounds__(128) k_pool(const float* __restrict__ a1W, const float* __restrict__ a1b,
                        const float* __restrict__ lng, const float* __restrict__ lnb,
                        const float* __restrict__ c1W, const float* __restrict__ c1b,
                        const float* __restrict__ c2W, const float* __restrict__ c2b,
                        float* __restrict__ out, int out_size) {
    __shared__ float s_w[64];
    __shared__ float s_g[HH], s_z[HH], s_c[64];
    __shared__ float sm[4];
    __shared__ int   s_last;
    int t = threadIdx.x;
    int r0 = blockIdx.x * 64;
    if (t < 64) s_w[t] = expf(g_rowsum[r0 + t] - g_red[0]) * (1.0f / g_red[1]);
    __syncthreads();
    float acc = 0.f;
    #pragma unroll 4
    for (int j = 0; j < 64; j++) acc += s_w[j] * g_h2[(r0 + j) * HH + t];
    atomicAdd(&g_graph[t], acc);

    __threadfence();
    if (t == 0) {
        int done = atomicAdd(&g_ctr1, 1);
        s_last = (done == (int)gridDim.x - 1);
    }
    __syncthreads();
    if (!s_last) return;

    s_g[t] = g_graph[t];
    __syncthreads();
    if (t < 64) {
        float a = a1b[t];
        #pragma unroll 8
        for (int k = 0; k < HH; k++) a += s_g[k] * a1W[k * 64 + t];
        g_af[t] = fmaxf(a, 0.f);
    }
    float v = s_g[t];
    #pragma unroll
    for (int o = 16; o > 0; o >>= 1) v += __shfl_down_sync(0xffffffffu, v, o);
    if ((t & 31) == 0) sm[t >> 5] = v;
    __syncthreads();
    float mu = (sm[0] + sm[1] + sm[2] + sm[3]) * (1.0f / HH);
    __syncthreads();
    float d = s_g[t] - mu;
    float v2 = d * d;
    #pragma unroll
    for (int o = 16; o > 0; o >>= 1) v2 += __shfl_down_sync(0xffffffffu, v2, o);
    if ((t & 31) == 0) sm[t >> 5] = v2;
    __syncthreads();
    float var = (sm[0] + sm[1] + sm[2] + sm[3]) * (1.0f / HH);
    s_z[t] = d / sqrtf(var + 1e-5f) * lng[t] + lnb[t];
    __syncthreads();
    if (t < 64) {
        float c = c1b[t];
        #pragma unroll 8
        for (int k = 0; k < HH; k++) c += s_z[k] * c1W[k * 64 + t];
        s_c[t] = fmaxf(c, 0.f);
    }
    __syncthreads();
    if (t == 0) {
        float val = c2b[0];
        #pragma unroll 8
        for (int j = 0; j < 64; j++) val += s_c[j] * c2W[j];
        if (out_size > NN) out[NN] = val;
        g_ctr1 = 0;
    }
}

// Actor logits; clears g_cnt and bumps g_gen for next launch;
// last block: softmax + output.
__global__ void __launch_bounds__(256) k_act(const float* __restrict__ a2W, const float* __restrict__ a2b,
                       float* __restrict__ out) {
    __shared__ float s_af[64];
    __shared__ float sm[8];
    __shared__ float s_bm;
    __shared__ int   s_last;
    int t = threadIdx.x;
    if (t < 64) s_af[t] = g_af[t];
    __syncthreads();
    int o = blockIdx.x * 256 + t;
    float acc = a2b[o];
    #pragma unroll
    for (int j = 0; j < 64; j++) acc += s_af[j] * a2W[j * AA + o];
    g_logits[o] = acc;
    g_cnt[o] = 0;               // clear degree array for next launch (AA == NN)

    __threadfence();
    if (t == 0) {
        int done = atomicAdd(&g_ctr2, 1);
        s_last = (done == (int)gridDim.x - 1);
    }
    __syncthreads();
    if (!s_last) return;

    if (t == 0) g_gen = g_gen + 1;   // fresh generation for next launch

    float m = -1e30f;
    for (int j = t; j < AA; j += 256) m = fmaxf(m, g_logits[j]);
    #pragma unroll
    for (int ofs = 16; ofs > 0; ofs >>= 1) m = fmaxf(m, __shfl_down_sync(0xffffffffu, m, ofs));
    if ((t & 31) == 0) sm[t >> 5] = m;
    __syncthreads();
    if (t == 0) {
        float x = sm[0];
        #pragma unroll
        for (int j = 1; j < 8; j++) x = fmaxf(x, sm[j]);
        s_bm = x;
    }
    __syncthreads();
    float bm = s_bm;
    float s = 0.f;
    for (int j = t; j < AA; j += 256) s += expf(g_logits[j] - bm);
    #pragma unroll
    for (int ofs = 16; ofs > 0; ofs >>= 1) s += __shfl_down_sync(0xffffffffu, s, ofs);
    __syncthreads();
    if ((t & 31) == 0) sm[t >> 5] = s;
    __syncthreads();
    if (t == 0) {
        float x = 0.f;
        #pragma unroll
        for (int j = 0; j < 8; j++) x += sm[j];
        s_bm = 1.0f / x;
        g_ctr2 = 0;
    }
    __syncthreads();
    float inv = s_bm;
    for (int j = t; j < AA; j += 256) out[j] = expf(g_logits[j] - bm) * inv;
}

// ---------------- launch ----------------
extern "C" void kernel_launch(void* const* d_in, const int* in_sizes, int n_in,
                              void* d_out, int out_size) {
    const float* x    = (const float*)d_in[0];
    const int*   ei   = (const int*)  d_in[1];
    int E = in_sizes[1] / 2;
    const float* g1W  = (const float*)d_in[2];
    const float* g1b  = (const float*)d_in[3];
    const float* g2W  = (const float*)d_in[4];
    const float* g2b  = (const float*)d_in[5];
    const float* resW = (const float*)d_in[6];
    const float* resb = (const float*)d_in[7];
    const float* a1W  = (const float*)d_in[8];
    const float* a1b  = (const float*)d_in[9];
    const float* a2W  = (const float*)d_in[10];
    const float* a2b  = (const float*)d_in[11];
    const float* lng  = (const float*)d_in[12];
    const float* lnb  = (const float*)d_in[13];
    const float* c1W  = (const float*)d_in[14];
    const float* c1b  = (const float*)d_in[15];
    const float* c2W  = (const float*)d_in[16];
    const float* c2b  = (const float*)d_in[17];
    float* out = (float*)d_out;

    const int SMEM96 = 96 * 1024;
    static int attr_done = 0;
    if (!attr_done) {
        cudaFuncSetAttribute(k_l1,    cudaFuncAttributeMaxDynamicSharedMemorySize, SMEM96);
        cudaFuncSetAttribute(k_gemm2, cudaFuncAttributeMaxDynamicSharedMemorySize, SMEM96);
        attr_done = 1;
    }

    k_dedup<<<(E + 255) / 256, 256>>>(ei, E);
    k_spmmx<<<NN / 4, 128>>>(x);
    k_l1   <<<NN / GROWS, 512, SMEM96>>>(x, g1W, g1b, resW, resb);
    k_gemm2<<<NN / GROWS, 512, SMEM96>>>(g2W);
    k_spmm2<<<NN / 4, 128>>>(g2b);
    k_pool <<<128, 128>>>(a1W, a1b, lng, lnb, c1W, c1b, c2W, c2b, out, out_size);
    k_act  <<<32, 256>>>(a2W, a2b, out);
}